// round 2
// baseline (speedup 1.0000x reference)
#include <cuda_runtime.h>
#include <math.h>

#define NSPIN 256
#define FDIM  64
#define BATCH 64
#define HP    8            // half-powers: chain u_1..u_8, B_1..B_8
#define PMAX  16           // series truncation: powers 0..16
#define NITER 40
#define JS_STRIDE 260      // [128][260] floats, 16B-aligned rows, bank-safe
#define AS_STRIDE 68       // [256][68] floats

// -------------------- device scratch (no runtime allocation) --------------------
__device__ float g_J[NSPIN * NSPIN];
__device__ float g_B[2][NSPIN * NSPIN];                 // ping-pong J^p
__device__ float g_U[2][BATCH * NSPIN * FDIM];          // ping-pong J^p h
__device__ float g_pAA_h[BATCH][HP];                    // ||u_p||^2
__device__ float g_pAC_h[BATCH][HP][2];                 // <u_p, u_{p+1}> partials (2 row tiles)
__device__ float g_pCC_h[BATCH][2];                     // ||u_HP||^2 partials
__device__ float g_pAA_t[HP][4];                        // ||B_p||_F^2 partials (4 col tiles)
__device__ float g_pAC_t[HP][2][4];                     // <B_p, B_{p+1}> partials
__device__ float g_pCC_t[2][4];                         // ||B_HP||_F^2 partials

// -------------------- helpers --------------------
__device__ __forceinline__ unsigned long long dup2(float a) {
    unsigned long long r;
    asm("mov.b64 %0, {%1, %1};" : "=l"(r) : "f"(a));
    return r;
}
__device__ __forceinline__ void fma2(unsigned long long& acc, unsigned long long a,
                                     unsigned long long b) {
    asm("fma.rn.f32x2 %0, %1, %2, %3;" : "=l"(acc) : "l"(a), "l"(b), "l"(acc));
}

__device__ __forceinline__ float blockReduceSum(float v, float* scratch) {
    #pragma unroll
    for (int o = 16; o > 0; o >>= 1) v += __shfl_down_sync(0xffffffffu, v, o);
    int lane = threadIdx.x & 31, w = threadIdx.x >> 5;
    if (lane == 0) scratch[w] = v;
    __syncthreads();
    float r = 0.f;
    if (w == 0) {
        r = (lane < 8) ? scratch[lane] : 0.f;
        #pragma unroll
        for (int o = 4; o > 0; o >>= 1) r += __shfl_down_sync(0xffffffffu, r, o);
    }
    __syncthreads();
    return r;   // valid in thread 0
}

// -------------------- kernel 1: J = symmetrize(J_raw), traceless; B_1 = J ------
__global__ void build_J(const float* __restrict__ Jr) {
    int i = blockIdx.x;
    int j = threadIdx.x;
    float v = (i == j) ? 0.f : 0.5f * (Jr[i * NSPIN + j] + Jr[j * NSPIN + i]);
    g_J[i * NSPIN + j] = v;
    g_B[1][i * NSPIN + j] = v;
}

// -------------------- kernel 2: one power step, fused dots ----------------------
// Blocks 0..127  : H-part.  b = bid>>1, rt = bid&1.  C[b] (256x64) = J @ A[b]
// Blocks 128..135: matrix part (skipped for s==0). rt = t>>2, ct = t&3.
//                  C (256x256) = J @ B_s
__global__ void __launch_bounds__(256, 1)
gemm_step(const float* __restrict__ x, int s, int last) {
    extern __shared__ float sh[];
    float* Js = sh;                               // [128][JS_STRIDE]
    float* As = sh + 128 * JS_STRIDE;             // [256][AS_STRIDE]

    const int bid = blockIdx.x;
    const int tid = threadIdx.x;

    bool isH;
    int b = 0, rt, ct, ncols, col0;
    const float* A;
    float* C;

    if (bid < 128) {
        isH = true;
        b = bid >> 1; rt = bid & 1; ct = 0;
        ncols = FDIM; col0 = 0;
        const float* base = (s == 0) ? x : g_U[(s + 1) & 1];
        A = base + (size_t)b * NSPIN * FDIM;
        C = g_U[s & 1] + (size_t)b * NSPIN * FDIM;
    } else {
        if (s == 0) return;
        isH = false;
        int t = bid - 128;
        rt = t >> 2; ct = t & 3;
        ncols = NSPIN; col0 = ct * 64;
        A = g_B[s & 1];
        C = g_B[(s + 1) & 1];
    }
    const int row0 = rt * 128;

    // stage J row-block [128][256]
    for (int idx = tid; idx < 128 * 64; idx += 256) {
        int r = idx >> 6, k4 = idx & 63;
        *(float4*)&Js[r * JS_STRIDE + k4 * 4] =
            *(const float4*)&g_J[(row0 + r) * NSPIN + k4 * 4];
    }
    // stage A col-slice [256][64]
    for (int idx = tid; idx < 256 * 16; idx += 256) {
        int k = idx >> 4, c4 = idx & 15;
        *(float4*)&As[k * AS_STRIDE + c4 * 4] =
            *(const float4*)&A[(size_t)k * ncols + col0 + c4 * 4];
    }
    __syncthreads();

    const int tx = tid & 7;    // col group: cols tx*8 .. tx*8+7
    const int ty = tid >> 3;   // row group: rows ty + 32*i, i=0..3

    unsigned long long acc[4][4];
    #pragma unroll
    for (int i = 0; i < 4; i++)
        #pragma unroll
        for (int j = 0; j < 4; j++) acc[i][j] = 0ull;

    const float* jsp0 = &Js[(ty +  0) * JS_STRIDE];
    const float* jsp1 = &Js[(ty + 32) * JS_STRIDE];
    const float* jsp2 = &Js[(ty + 64) * JS_STRIDE];
    const float* jsp3 = &Js[(ty + 96) * JS_STRIDE];
    const float* asp  = &As[tx * 8];

    #pragma unroll 4
    for (int k = 0; k < 256; ++k) {
        unsigned long long bv0 = *(const unsigned long long*)&asp[k * AS_STRIDE + 0];
        unsigned long long bv1 = *(const unsigned long long*)&asp[k * AS_STRIDE + 2];
        unsigned long long bv2 = *(const unsigned long long*)&asp[k * AS_STRIDE + 4];
        unsigned long long bv3 = *(const unsigned long long*)&asp[k * AS_STRIDE + 6];
        unsigned long long a0 = dup2(jsp0[k]);
        unsigned long long a1 = dup2(jsp1[k]);
        unsigned long long a2 = dup2(jsp2[k]);
        unsigned long long a3 = dup2(jsp3[k]);
        fma2(acc[0][0], a0, bv0); fma2(acc[0][1], a0, bv1);
        fma2(acc[0][2], a0, bv2); fma2(acc[0][3], a0, bv3);
        fma2(acc[1][0], a1, bv0); fma2(acc[1][1], a1, bv1);
        fma2(acc[1][2], a1, bv2); fma2(acc[1][3], a1, bv3);
        fma2(acc[2][0], a2, bv0); fma2(acc[2][1], a2, bv1);
        fma2(acc[2][2], a2, bv2); fma2(acc[2][3], a2, bv3);
        fma2(acc[3][0], a3, bv0); fma2(acc[3][1], a3, bv1);
        fma2(acc[3][2], a3, bv2); fma2(acc[3][3], a3, bv3);
    }

    // epilogue: store C, fused dots <A,C>, (opt) <C,C>
    float ac = 0.f, cc = 0.f;
    #pragma unroll
    for (int i = 0; i < 4; i++) {
        int r = row0 + ty + 32 * i;     // global row index (= k-index of A)
        #pragma unroll
        for (int j = 0; j < 4; j++) {
            float lo = __uint_as_float((unsigned)(acc[i][j] & 0xffffffffull));
            float hi = __uint_as_float((unsigned)(acc[i][j] >> 32));
            int c = tx * 8 + 2 * j;
            C[(size_t)r * ncols + col0 + c]     = lo;
            C[(size_t)r * ncols + col0 + c + 1] = hi;
            float alo = As[r * AS_STRIDE + c];
            float ahi = As[r * AS_STRIDE + c + 1];
            ac += lo * alo + hi * ahi;
            if (last) cc += lo * lo + hi * hi;
        }
    }
    // <A,A> over the full staged slice (only rt==0 blocks; avoids double count)
    float aa = 0.f;
    if (rt == 0) {
        for (int idx = tid; idx < 256 * 64; idx += 256) {
            int k = idx >> 6, c = idx & 63;
            float v = As[k * AS_STRIDE + c];
            aa += v * v;
        }
    }

    __syncthreads();                 // Js region now reusable as scratch
    float* scratch = sh;

    float acr = blockReduceSum(ac, scratch);
    if (tid == 0) {
        if (isH) g_pAC_h[b][s][rt] = acr;
        else     g_pAC_t[s][rt][ct] = acr;
    }
    float aar = blockReduceSum(aa, scratch);
    if (tid == 0 && rt == 0) {
        if (isH) g_pAA_h[b][s] = aar;
        else     g_pAA_t[s][ct] = aar;
    }
    if (last) {
        float ccr = blockReduceSum(cc, scratch);
        if (tid == 0) {
            if (isH) g_pCC_h[b][rt] = ccr;
            else     g_pCC_t[rt][ct] = ccr;
        }
    }
}

// -------------------- kernel 3: Newton + phi + afe (scalar, per batch) ---------
__global__ void newton_kernel(float* __restrict__ out, int out_size) {
    int b = threadIdx.x;
    if (b >= BATCH) return;

    double m[PMAX + 1], tp[PMAX + 1];
    #pragma unroll
    for (int ss = 0; ss < HP; ss++) {
        m[2 * ss]     = (double)g_pAA_h[b][ss];
        m[2 * ss + 1] = (double)g_pAC_h[b][ss][0] + (double)g_pAC_h[b][ss][1];
    }
    m[PMAX] = (double)g_pCC_h[b][0] + (double)g_pCC_h[b][1];

    tp[0] = (double)NSPIN;   // tr(I)
    tp[1] = 0.0;             // tr(J) = 0 (traceless)
    #pragma unroll
    for (int ss = 1; ss < HP; ss++) {
        double a = 0.0, c = 0.0;
        #pragma unroll
        for (int q = 0; q < 4; q++) a += (double)g_pAA_t[ss][q];
        #pragma unroll
        for (int r = 0; r < 2; r++)
            #pragma unroll
            for (int q = 0; q < 4; q++) c += (double)g_pAC_t[ss][r][q];
        tp[2 * ss] = a;
        tp[2 * ss + 1] = c;
    }
    {
        double c = 0.0;
        #pragma unroll
        for (int r = 0; r < 2; r++)
            #pragma unroll
            for (int q = 0; q < 4; q++) c += (double)g_pCC_t[r][q];
        tp[PMAX] = c;
    }

    // Newton: g(t) = beta*N - 0.5*tr(V^-1) - (beta/4D) * h^T V^-2 h, V = tI - J
    double t = 1.0;
    for (int it = 0; it < NITER; ++it) {
        double xv = 1.0 / t;
        double Sa = 0.0, Sb = 0.0, Qb = 0.0, Qc = 0.0;
        #pragma unroll
        for (int p = PMAX; p >= 0; --p) {
            Sa = Sa * xv + tp[p];
            Sb = Sb * xv + (double)(p + 1) * tp[p];
            Qb = Qb * xv + (double)(p + 1) * m[p];
            Qc = Qc * xv + 0.5 * (double)(p + 1) * (double)(p + 2) * m[p];
        }
        double s1 = xv * Sa;              // tr(V^-1)
        double s2 = xv * xv * Sb;         // tr(V^-2)
        double q2 = xv * xv * Qb;         // h^T V^-2 h
        double q3 = xv * xv * xv * Qc;    // h^T V^-3 h
        double g  = 256.0 - 0.5 * s1 - q2 / 256.0;
        double gp = 0.5 * s2 + q3 / 128.0;
        if (fabs(g) > 1e-4) t -= g / gp;
    }

    // phi(t*) = beta*N*t - 0.5*logdet(V) + (beta/4D)*h^T V^-1 h
    double xv = 1.0 / t;
    double Qa = 0.0;
    #pragma unroll
    for (int p = PMAX; p >= 0; --p) Qa = Qa * xv + m[p];
    double q1 = xv * Qa;
    double lds = 0.0;
    #pragma unroll
    for (int p = PMAX; p >= 1; --p) lds = lds * xv + tp[p] / (double)p;
    lds *= xv;
    double logdet = 256.0 * log(t) - lds;
    double phi = 256.0 * t - 0.5 * logdet + q1 / 256.0;
    double afe = -(0.5 * log(3.14159265358979323846) + phi / 256.0);

    out[b] = (float)afe;
    if (out_size >= 2 * BATCH) out[BATCH + b] = (float)t;
}

// -------------------- launch --------------------
extern "C" void kernel_launch(void* const* d_in, const int* in_sizes, int n_in,
                              void* d_out, int out_size) {
    const float* x  = (const float*)d_in[0];   // (64, 256, 64)
    const float* Jr = (const float*)d_in[1];   // (256, 256)
    float* out = (float*)d_out;

    size_t shmem = (size_t)(128 * JS_STRIDE + 256 * AS_STRIDE) * sizeof(float);
    cudaFuncSetAttribute(gemm_step, cudaFuncAttributeMaxDynamicSharedMemorySize,
                         (int)shmem);

    build_J<<<NSPIN, NSPIN>>>(Jr);
    for (int s = 0; s < HP; ++s)
        gemm_step<<<136, 256, shmem>>>(x, s, (s == HP - 1) ? 1 : 0);
    newton_kernel<<<1, 64>>>(out, out_size);
}

// round 3
// speedup vs baseline: 1.9815x; 1.9815x over previous
#include <cuda_runtime.h>
#include <math.h>

#define NSPIN 256
#define FDIM  64
#define BATCH 64
#define HP    4            // half-powers: chain u_1..u_4, B_1..B_4
#define PMAX  8            // series truncation: powers 0..8 (tail ~0.155^9, negligible)
#define NITER 40
#define JS_STRIDE 260      // [128][260] floats, 16B-aligned rows
#define AS_STRIDE 68       // [256][68] floats, 16B-aligned rows

// -------------------- device scratch (no runtime allocation) --------------------
__device__ float g_J[NSPIN * NSPIN];
__device__ float g_B[2][NSPIN * NSPIN];                 // ping-pong J^p
__device__ float g_U[2][BATCH * NSPIN * FDIM];          // ping-pong J^p h
__device__ float g_pAA_h[BATCH][HP];                    // ||u_p||^2
__device__ float g_pAC_h[BATCH][HP][2];                 // <u_p, u_{p+1}> partials (2 row tiles)
__device__ float g_pCC_h[BATCH][2];                     // ||u_HP||^2 partials
__device__ float g_pAA_t[HP][4];                        // ||B_p||_F^2 partials (4 col tiles)
__device__ float g_pAC_t[HP][2][4];                     // <B_p, B_{p+1}> partials
__device__ float g_pCC_t[2][4];                         // ||B_HP||_F^2 partials

// -------------------- helpers --------------------
__device__ __forceinline__ unsigned long long dup2(float a) {
    unsigned long long r;
    asm("mov.b64 %0, {%1, %1};" : "=l"(r) : "f"(a));
    return r;
}
__device__ __forceinline__ void fma2(unsigned long long& acc, unsigned long long a,
                                     unsigned long long b) {
    asm("fma.rn.f32x2 %0, %1, %2, %3;" : "=l"(acc) : "l"(a), "l"(b), "l"(acc));
}
__device__ __forceinline__ float lo32(unsigned long long v) {
    return __uint_as_float((unsigned)(v & 0xffffffffull));
}
__device__ __forceinline__ float hi32(unsigned long long v) {
    return __uint_as_float((unsigned)(v >> 32));
}

__device__ __forceinline__ float blockReduceSum(float v, float* scratch) {
    #pragma unroll
    for (int o = 16; o > 0; o >>= 1) v += __shfl_down_sync(0xffffffffu, v, o);
    int lane = threadIdx.x & 31, w = threadIdx.x >> 5;
    if (lane == 0) scratch[w] = v;
    __syncthreads();
    float r = 0.f;
    if (w == 0) {
        r = (lane < 8) ? scratch[lane] : 0.f;
        #pragma unroll
        for (int o = 4; o > 0; o >>= 1) r += __shfl_down_sync(0xffffffffu, r, o);
    }
    __syncthreads();
    return r;   // valid in thread 0
}

// -------------------- kernel 1: J = symmetrize(J_raw), traceless; B_1 = J ------
__global__ void build_J(const float* __restrict__ Jr) {
    int i = blockIdx.x;
    int j = threadIdx.x;
    float v = (i == j) ? 0.f : 0.5f * (Jr[i * NSPIN + j] + Jr[j * NSPIN + i]);
    g_J[i * NSPIN + j] = v;
    g_B[1][i * NSPIN + j] = v;
}

// -------------------- kernel 2: one power step, fused dots ----------------------
// Blocks 0..127  : H-part.  b = bid>>1, rt = bid&1.  C[b] (256x64) = J @ A[b]
// Blocks 128..135: matrix part (skipped for s==0). rt = t>>2, ct = t&3.
//                  C (256x256) = J @ B_s
__global__ void __launch_bounds__(256, 1)
gemm_step(const float* __restrict__ x, int s, int last) {
    extern __shared__ float sh[];
    float* Js = sh;                               // [128][JS_STRIDE]
    float* As = sh + 128 * JS_STRIDE;             // [256][AS_STRIDE]

    const int bid = blockIdx.x;
    const int tid = threadIdx.x;

    bool isH;
    int b = 0, rt, ct, ncols, col0;
    const float* A;
    float* C;

    if (bid < 128) {
        isH = true;
        b = bid >> 1; rt = bid & 1; ct = 0;
        ncols = FDIM; col0 = 0;
        const float* base = (s == 0) ? x : g_U[(s + 1) & 1];
        A = base + (size_t)b * NSPIN * FDIM;
        C = g_U[s & 1] + (size_t)b * NSPIN * FDIM;
    } else {
        if (s == 0) return;
        isH = false;
        int t = bid - 128;
        rt = t >> 2; ct = t & 3;
        ncols = NSPIN; col0 = ct * 64;
        A = g_B[s & 1];
        C = g_B[(s + 1) & 1];
    }
    const int row0 = rt * 128;

    // stage J row-block [128][256]
    for (int idx = tid; idx < 128 * 64; idx += 256) {
        int r = idx >> 6, k4 = idx & 63;
        *(float4*)&Js[r * JS_STRIDE + k4 * 4] =
            *(const float4*)&g_J[(row0 + r) * NSPIN + k4 * 4];
    }
    // stage A col-slice [256][64]
    for (int idx = tid; idx < 256 * 16; idx += 256) {
        int k = idx >> 4, c4 = idx & 15;
        *(float4*)&As[k * AS_STRIDE + c4 * 4] =
            *(const float4*)&A[(size_t)k * ncols + col0 + c4 * 4];
    }
    __syncthreads();

    const int tx = tid & 7;    // col group: cols tx*8 .. tx*8+7
    const int ty = tid >> 3;   // row group: rows ty + 32*i, i=0..3

    unsigned long long acc[4][4];
    #pragma unroll
    for (int i = 0; i < 4; i++)
        #pragma unroll
        for (int j = 0; j < 4; j++) acc[i][j] = 0ull;

    const float* jsp0 = &Js[(ty +  0) * JS_STRIDE];
    const float* jsp1 = &Js[(ty + 32) * JS_STRIDE];
    const float* jsp2 = &Js[(ty + 64) * JS_STRIDE];
    const float* jsp3 = &Js[(ty + 96) * JS_STRIDE];
    const float* asp  = &As[tx * 8];

    // main loop: 4-k chunks; J rows via 1 LDS.128 per row per chunk,
    // B operands via 2 LDS.128 per k straight into 64-bit f32x2 registers.
    #pragma unroll 2
    for (int kk = 0; kk < 256; kk += 4) {
        float4 j0 = *(const float4*)&jsp0[kk];
        float4 j1 = *(const float4*)&jsp1[kk];
        float4 j2 = *(const float4*)&jsp2[kk];
        float4 j3 = *(const float4*)&jsp3[kk];
        const float* ap = &asp[kk * AS_STRIDE];
        #pragma unroll
        for (int u = 0; u < 4; ++u) {
            ulonglong2 bA = *(const ulonglong2*)&ap[u * AS_STRIDE];     // cols 0..3
            ulonglong2 bB = *(const ulonglong2*)&ap[u * AS_STRIDE + 4]; // cols 4..7
            float j0u = (u == 0) ? j0.x : (u == 1) ? j0.y : (u == 2) ? j0.z : j0.w;
            float j1u = (u == 0) ? j1.x : (u == 1) ? j1.y : (u == 2) ? j1.z : j1.w;
            float j2u = (u == 0) ? j2.x : (u == 1) ? j2.y : (u == 2) ? j2.z : j2.w;
            float j3u = (u == 0) ? j3.x : (u == 1) ? j3.y : (u == 2) ? j3.z : j3.w;
            unsigned long long a0 = dup2(j0u);
            unsigned long long a1 = dup2(j1u);
            unsigned long long a2 = dup2(j2u);
            unsigned long long a3 = dup2(j3u);
            fma2(acc[0][0], a0, bA.x); fma2(acc[0][1], a0, bA.y);
            fma2(acc[0][2], a0, bB.x); fma2(acc[0][3], a0, bB.y);
            fma2(acc[1][0], a1, bA.x); fma2(acc[1][1], a1, bA.y);
            fma2(acc[1][2], a1, bB.x); fma2(acc[1][3], a1, bB.y);
            fma2(acc[2][0], a2, bA.x); fma2(acc[2][1], a2, bA.y);
            fma2(acc[2][2], a2, bB.x); fma2(acc[2][3], a2, bB.y);
            fma2(acc[3][0], a3, bA.x); fma2(acc[3][1], a3, bA.y);
            fma2(acc[3][2], a3, bB.x); fma2(acc[3][3], a3, bB.y);
        }
    }

    // epilogue: vectorized store of C, fused dots <A,C>, (opt) <C,C>
    float ac = 0.f, cc = 0.f;
    #pragma unroll
    for (int i = 0; i < 4; i++) {
        int r = row0 + ty + 32 * i;     // global row index (= k-index of A)
        float c0 = lo32(acc[i][0]), c1 = hi32(acc[i][0]);
        float c2 = lo32(acc[i][1]), c3 = hi32(acc[i][1]);
        float c4 = lo32(acc[i][2]), c5 = hi32(acc[i][2]);
        float c6 = lo32(acc[i][3]), c7 = hi32(acc[i][3]);
        float* cp = &C[(size_t)r * ncols + col0 + tx * 8];
        *(float4*)cp       = make_float4(c0, c1, c2, c3);
        *(float4*)(cp + 4) = make_float4(c4, c5, c6, c7);
        const float* arow = &As[r * AS_STRIDE + tx * 8];
        float a0 = arow[0], a1 = arow[1], a2 = arow[2], a3 = arow[3];
        float a4 = arow[4], a5 = arow[5], a6 = arow[6], a7 = arow[7];
        ac += c0 * a0 + c1 * a1 + c2 * a2 + c3 * a3
            + c4 * a4 + c5 * a5 + c6 * a6 + c7 * a7;
        if (last) cc += c0 * c0 + c1 * c1 + c2 * c2 + c3 * c3
                      + c4 * c4 + c5 * c5 + c6 * c6 + c7 * c7;
    }
    // <A,A> over the full staged slice (only rt==0 blocks; avoids double count)
    float aa = 0.f;
    if (rt == 0) {
        for (int idx = tid; idx < 256 * 64; idx += 256) {
            int k = idx >> 6, c = idx & 63;
            float v = As[k * AS_STRIDE + c];
            aa += v * v;
        }
    }

    __syncthreads();                 // Js region now reusable as scratch
    float* scratch = sh;

    float acr = blockReduceSum(ac, scratch);
    if (tid == 0) {
        if (isH) g_pAC_h[b][s][rt] = acr;
        else     g_pAC_t[s][rt][ct] = acr;
    }
    float aar = blockReduceSum(aa, scratch);
    if (tid == 0 && rt == 0) {
        if (isH) g_pAA_h[b][s] = aar;
        else     g_pAA_t[s][ct] = aar;
    }
    if (last) {
        float ccr = blockReduceSum(cc, scratch);
        if (tid == 0) {
            if (isH) g_pCC_h[b][rt] = ccr;
            else     g_pCC_t[rt][ct] = ccr;
        }
    }
}

// -------------------- kernel 3: Newton + phi + afe (scalar, per batch) ---------
__global__ void newton_kernel(float* __restrict__ out, int out_size) {
    int b = threadIdx.x;
    if (b >= BATCH) return;

    double m[PMAX + 1], tp[PMAX + 1];
    #pragma unroll
    for (int ss = 0; ss < HP; ss++) {
        m[2 * ss]     = (double)g_pAA_h[b][ss];
        m[2 * ss + 1] = (double)g_pAC_h[b][ss][0] + (double)g_pAC_h[b][ss][1];
    }
    m[PMAX] = (double)g_pCC_h[b][0] + (double)g_pCC_h[b][1];

    tp[0] = (double)NSPIN;   // tr(I)
    tp[1] = 0.0;             // tr(J) = 0 (traceless)
    #pragma unroll
    for (int ss = 1; ss < HP; ss++) {
        double a = 0.0, c = 0.0;
        #pragma unroll
        for (int q = 0; q < 4; q++) a += (double)g_pAA_t[ss][q];
        #pragma unroll
        for (int r = 0; r < 2; r++)
            #pragma unroll
            for (int q = 0; q < 4; q++) c += (double)g_pAC_t[ss][r][q];
        tp[2 * ss] = a;
        tp[2 * ss + 1] = c;
    }
    {
        double c = 0.0;
        #pragma unroll
        for (int r = 0; r < 2; r++)
            #pragma unroll
            for (int q = 0; q < 4; q++) c += (double)g_pCC_t[r][q];
        tp[PMAX] = c;
    }

    // Newton: g(t) = beta*N - 0.5*tr(V^-1) - (beta/4D) * h^T V^-2 h, V = tI - J
    double t = 1.0;
    for (int it = 0; it < NITER; ++it) {
        double xv = 1.0 / t;
        double Sa = 0.0, Sb = 0.0, Qb = 0.0, Qc = 0.0;
        #pragma unroll
        for (int p = PMAX; p >= 0; --p) {
            Sa = Sa * xv + tp[p];
            Sb = Sb * xv + (double)(p + 1) * tp[p];
            Qb = Qb * xv + (double)(p + 1) * m[p];
            Qc = Qc * xv + 0.5 * (double)(p + 1) * (double)(p + 2) * m[p];
        }
        double s1 = xv * Sa;              // tr(V^-1)
        double s2 = xv * xv * Sb;         // tr(V^-2)
        double q2 = xv * xv * Qb;         // h^T V^-2 h
        double q3 = xv * xv * xv * Qc;    // h^T V^-3 h
        double g  = 256.0 - 0.5 * s1 - q2 / 256.0;
        double gp = 0.5 * s2 + q3 / 128.0;
        if (fabs(g) > 1e-4) t -= g / gp;
    }

    // phi(t*) = beta*N*t - 0.5*logdet(V) + (beta/4D)*h^T V^-1 h
    double xv = 1.0 / t;
    double Qa = 0.0;
    #pragma unroll
    for (int p = PMAX; p >= 0; --p) Qa = Qa * xv + m[p];
    double q1 = xv * Qa;
    double lds = 0.0;
    #pragma unroll
    for (int p = PMAX; p >= 1; --p) lds = lds * xv + tp[p] / (double)p;
    lds *= xv;
    double logdet = 256.0 * log(t) - lds;
    double phi = 256.0 * t - 0.5 * logdet + q1 / 256.0;
    double afe = -(0.5 * log(3.14159265358979323846) + phi / 256.0);

    out[b] = (float)afe;
    if (out_size >= 2 * BATCH) out[BATCH + b] = (float)t;
}

// -------------------- launch --------------------
extern "C" void kernel_launch(void* const* d_in, const int* in_sizes, int n_in,
                              void* d_out, int out_size) {
    const float* x  = (const float*)d_in[0];   // (64, 256, 64)
    const float* Jr = (const float*)d_in[1];   // (256, 256)
    float* out = (float*)d_out;

    size_t shmem = (size_t)(128 * JS_STRIDE + 256 * AS_STRIDE) * sizeof(float);
    cudaFuncSetAttribute(gemm_step, cudaFuncAttributeMaxDynamicSharedMemorySize,
                         (int)shmem);

    build_J<<<NSPIN, NSPIN>>>(Jr);
    for (int s = 0; s < HP; ++s)
        gemm_step<<<136, 256, shmem>>>(x, s, (s == HP - 1) ? 1 : 0);
    newton_kernel<<<1, 64>>>(out, out_size);
}

// round 5
// speedup vs baseline: 6.1873x; 3.1226x over previous
#include <cuda_runtime.h>
#include <math.h>

#define NSPIN 256
#define FDIM  64
#define BATCH 64
#define PMAX  4            // series truncation: powers 0..4 (tail ~1e-6 effect)
#define NITER 40
#define TOL   1e-4
#define JS_STRIDE 260      // [128][260] floats: lane stride 260 -> conflict-free LDS.128
#define AS_STRIDE 68       // [256][68] floats

// -------------------- device scratch (no runtime allocation) --------------------
__device__ float g_J[NSPIN * NSPIN];
__device__ float g_B2[NSPIN * NSPIN];                   // J^2
__device__ float g_U1[BATCH * NSPIN * FDIM];            // J h
__device__ float g_U2[BATCH * NSPIN * FDIM];            // J^2 h
__device__ float g_pAA_h[BATCH][2];                     // s=0: ||h||^2, s=1: ||u1||^2
__device__ float g_pAC_h[BATCH][2][2];                  // s=0: <h,u1>, s=1: <u1,u2> (2 row tiles)
__device__ float g_pCC_h[BATCH][2];                     // ||u2||^2 partials
__device__ float g_pAA_t[4];                            // ||J||_F^2 partials (4 col tiles)
__device__ float g_pAC_t[2][4];                         // tr(J^3) partials
__device__ float g_pCC_t[2][4];                         // tr(J^4) partials

// -------------------- helpers --------------------
__device__ __forceinline__ unsigned long long dup2(float a) {
    unsigned long long r;
    asm("mov.b64 %0, {%1, %1};" : "=l"(r) : "f"(a));
    return r;
}
__device__ __forceinline__ void fma2(unsigned long long& acc, unsigned long long a,
                                     unsigned long long b) {
    asm("fma.rn.f32x2 %0, %1, %2, %3;" : "=l"(acc) : "l"(a), "l"(b), "l"(acc));
}
__device__ __forceinline__ float lo32(unsigned long long v) {
    return __uint_as_float((unsigned)(v & 0xffffffffull));
}
__device__ __forceinline__ float hi32(unsigned long long v) {
    return __uint_as_float((unsigned)(v >> 32));
}

// block reduce for 512 threads (16 warps)
__device__ __forceinline__ float blockReduceSum(float v, float* scratch) {
    #pragma unroll
    for (int o = 16; o > 0; o >>= 1) v += __shfl_down_sync(0xffffffffu, v, o);
    int lane = threadIdx.x & 31, w = threadIdx.x >> 5;
    if (lane == 0) scratch[w] = v;
    __syncthreads();
    float r = 0.f;
    if (w == 0) {
        r = (lane < 16) ? scratch[lane] : 0.f;
        #pragma unroll
        for (int o = 8; o > 0; o >>= 1) r += __shfl_down_sync(0xffffffffu, r, o);
    }
    __syncthreads();
    return r;   // valid in thread 0
}

// -------------------- kernel 1: J = symmetrize(J_raw), traceless ---------------
__global__ void build_J(const float* __restrict__ Jr) {
    int i = blockIdx.x;
    int j = threadIdx.x;
    float v = (i == j) ? 0.f : 0.5f * (Jr[i * NSPIN + j] + Jr[j * NSPIN + i]);
    g_J[i * NSPIN + j] = v;
}

// -------------------- kernel 2: one power step, fused dots ----------------------
// Blocks 0..127  : H-part.  b = bid>>1, rt = bid&1.  C[b] (256x64) = J @ A[b]
// Blocks 128..135: matrix part (only s==1). rt = t>>2, ct = t&3.
//                  C (256x256) = J @ J
__global__ void __launch_bounds__(512, 1)
gemm_step(const float* __restrict__ x, int s) {
    extern __shared__ float sh[];
    float* Js = sh;                               // [128][JS_STRIDE]
    float* As = sh + 128 * JS_STRIDE;             // [256][AS_STRIDE]

    const int bid = blockIdx.x;
    const int tid = threadIdx.x;
    const int last = s;                           // s==1 is the last step

    bool isH;
    int b = 0, rt, ct, ncols, col0;
    const float* A;
    float* C;

    if (bid < 128) {
        isH = true;
        b = bid >> 1; rt = bid & 1; ct = 0;
        ncols = FDIM; col0 = 0;
        A = ((s == 0) ? x : g_U1) + (size_t)b * NSPIN * FDIM;
        C = ((s == 0) ? g_U1 : g_U2) + (size_t)b * NSPIN * FDIM;
    } else {
        isH = false;
        int t = bid - 128;
        rt = t >> 2; ct = t & 3;
        ncols = NSPIN; col0 = ct * 64;
        A = g_J;
        C = g_B2;
    }
    const int row0 = rt * 128;

    // stage J row-block [128][256]
    for (int idx = tid; idx < 128 * 64; idx += 512) {
        int r = idx >> 6, k4 = idx & 63;
        *(float4*)&Js[r * JS_STRIDE + k4 * 4] =
            *(const float4*)&g_J[(row0 + r) * NSPIN + k4 * 4];
    }
    // stage A col-slice [256][64]
    for (int idx = tid; idx < 256 * 16; idx += 512) {
        int k = idx >> 4, c4 = idx & 15;
        *(float4*)&As[k * AS_STRIDE + c4 * 4] =
            *(const float4*)&A[(size_t)k * ncols + col0 + c4 * 4];
    }
    __syncthreads();

    // thread map: ty = tid&63 (row), tx = tid>>6 (col group of 8)
    // -> B loads are warp-broadcast (1 wavefront), J loads conflict-free.
    const int ty = tid & 63;
    const int tx = tid >> 6;

    unsigned long long acc[2][4];
    #pragma unroll
    for (int i = 0; i < 2; i++)
        #pragma unroll
        for (int j = 0; j < 4; j++) acc[i][j] = 0ull;

    const float* jr0 = &Js[ty * JS_STRIDE];
    const float* jr1 = &Js[(ty + 64) * JS_STRIDE];
    const float* bcol = &As[tx * 8];

    #pragma unroll 2
    for (int kk = 0; kk < 256; kk += 4) {
        float4 ja = *(const float4*)&jr0[kk];
        float4 jb = *(const float4*)&jr1[kk];
        #pragma unroll
        for (int u = 0; u < 4; ++u) {
            ulonglong2 b0 = *(const ulonglong2*)&bcol[(kk + u) * AS_STRIDE];
            ulonglong2 b1 = *(const ulonglong2*)&bcol[(kk + u) * AS_STRIDE + 4];
            float jav = (u == 0) ? ja.x : (u == 1) ? ja.y : (u == 2) ? ja.z : ja.w;
            float jbv = (u == 0) ? jb.x : (u == 1) ? jb.y : (u == 2) ? jb.z : jb.w;
            unsigned long long a0 = dup2(jav);
            unsigned long long a1 = dup2(jbv);
            fma2(acc[0][0], a0, b0.x); fma2(acc[0][1], a0, b0.y);
            fma2(acc[0][2], a0, b1.x); fma2(acc[0][3], a0, b1.y);
            fma2(acc[1][0], a1, b0.x); fma2(acc[1][1], a1, b0.y);
            fma2(acc[1][2], a1, b1.x); fma2(acc[1][3], a1, b1.y);
        }
    }

    // epilogue: store C, fused dots <A,C>, (opt) <C,C>
    float ac = 0.f, cc = 0.f;
    #pragma unroll
    for (int i = 0; i < 2; i++) {
        int r = row0 + ty + 64 * i;     // global row index (= k-index of A)
        float c0 = lo32(acc[i][0]), c1 = hi32(acc[i][0]);
        float c2 = lo32(acc[i][1]), c3 = hi32(acc[i][1]);
        float c4 = lo32(acc[i][2]), c5 = hi32(acc[i][2]);
        float c6 = lo32(acc[i][3]), c7 = hi32(acc[i][3]);
        float* cp = &C[(size_t)r * ncols + col0 + tx * 8];
        *(float4*)cp       = make_float4(c0, c1, c2, c3);
        *(float4*)(cp + 4) = make_float4(c4, c5, c6, c7);
        const float* arow = &As[r * AS_STRIDE + tx * 8];
        ac += c0 * arow[0] + c1 * arow[1] + c2 * arow[2] + c3 * arow[3]
            + c4 * arow[4] + c5 * arow[5] + c6 * arow[6] + c7 * arow[7];
        if (last) cc += c0 * c0 + c1 * c1 + c2 * c2 + c3 * c3
                      + c4 * c4 + c5 * c5 + c6 * c6 + c7 * c7;
    }
    // <A,A> over the full staged slice (rt==0 blocks only; avoids double count)
    float aa = 0.f;
    if (rt == 0) {
        for (int idx = tid; idx < 256 * 64; idx += 512) {
            int k = idx >> 6, c = idx & 63;
            float v = As[k * AS_STRIDE + c];
            aa += v * v;
        }
    }

    __syncthreads();                 // Js region now reusable as scratch
    float* scratch = sh;

    float acr = blockReduceSum(ac, scratch);
    if (tid == 0) {
        if (isH) g_pAC_h[b][s][rt] = acr;
        else     g_pAC_t[rt][ct] = acr;
    }
    float aar = blockReduceSum(aa, scratch);
    if (tid == 0 && rt == 0) {
        if (isH) g_pAA_h[b][s] = aar;
        else     g_pAA_t[ct] = aar;
    }
    if (last) {
        float ccr = blockReduceSum(cc, scratch);
        if (tid == 0) {
            if (isH) g_pCC_h[b][rt] = ccr;
            else     g_pCC_t[rt][ct] = ccr;
        }
    }
}

// -------------------- kernel 3: Newton + phi + afe (scalar, per batch) ---------
__global__ void newton_kernel(float* __restrict__ out, int out_size) {
    int b = threadIdx.x;
    if (b >= BATCH) return;

    double m[PMAX + 1], tp[PMAX + 1];
    m[0] = (double)g_pAA_h[b][0];
    m[1] = (double)g_pAC_h[b][0][0] + (double)g_pAC_h[b][0][1];
    m[2] = (double)g_pAA_h[b][1];
    m[3] = (double)g_pAC_h[b][1][0] + (double)g_pAC_h[b][1][1];
    m[4] = (double)g_pCC_h[b][0] + (double)g_pCC_h[b][1];

    tp[0] = (double)NSPIN;   // tr(I)
    tp[1] = 0.0;             // tr(J) = 0 (traceless)
    {
        double a = 0.0, c3 = 0.0, c4 = 0.0;
        #pragma unroll
        for (int q = 0; q < 4; q++) a += (double)g_pAA_t[q];
        #pragma unroll
        for (int r = 0; r < 2; r++)
            #pragma unroll
            for (int q = 0; q < 4; q++) {
                c3 += (double)g_pAC_t[r][q];
                c4 += (double)g_pCC_t[r][q];
            }
        tp[2] = a; tp[3] = c3; tp[4] = c4;
    }

    // folded Horner coefficients
    double cSa[PMAX + 1], cSb[PMAX + 1], cQb[PMAX + 1], cQc[PMAX + 1];
    #pragma unroll
    for (int p = 0; p <= PMAX; ++p) {
        cSa[p] = tp[p];
        cSb[p] = (double)(p + 1) * tp[p];
        cQb[p] = (double)(p + 1) * m[p];
        cQc[p] = 0.5 * (double)(p + 1) * (double)(p + 2) * m[p];
    }

    // Newton: g(t) = beta*N - 0.5*tr(V^-1) - (beta/4D) * h^T V^-2 h, V = tI - J
    double t = 1.0;
    for (int it = 0; it < NITER; ++it) {
        double xv = 1.0 / t;
        double Sa = 0.0, Sb = 0.0, Qb = 0.0, Qc = 0.0;
        #pragma unroll
        for (int p = PMAX; p >= 0; --p) {
            Sa = Sa * xv + cSa[p];
            Sb = Sb * xv + cSb[p];
            Qb = Qb * xv + cQb[p];
            Qc = Qc * xv + cQc[p];
        }
        double s1 = xv * Sa;              // tr(V^-1)
        double s2 = xv * xv * Sb;         // tr(V^-2)
        double q2 = xv * xv * Qb;         // h^T V^-2 h
        double q3 = xv * xv * xv * Qc;    // h^T V^-3 h
        double g  = 256.0 - 0.5 * s1 - q2 / 256.0;
        if (fabs(g) <= TOL) break;        // reference's update is 0 from here on
        double gp = 0.5 * s2 + q3 / 128.0;
        t -= g / gp;
    }

    // phi(t*) = beta*N*t - 0.5*logdet(V) + (beta/4D)*h^T V^-1 h
    double xv = 1.0 / t;
    double Qa = 0.0;
    #pragma unroll
    for (int p = PMAX; p >= 0; --p) Qa = Qa * xv + m[p];
    double q1 = xv * Qa;
    double lds = 0.0;
    #pragma unroll
    for (int p = PMAX; p >= 1; --p) lds = lds * xv + tp[p] / (double)p;
    lds *= xv;
    double logdet = 256.0 * log(t) - lds;
    double phi = 256.0 * t - 0.5 * logdet + q1 / 256.0;
    double afe = -(0.5 * log(3.14159265358979323846) + phi / 256.0);

    out[b] = (float)afe;
    if (out_size >= 2 * BATCH) out[BATCH + b] = (float)t;
}

// -------------------- launch --------------------
extern "C" void kernel_launch(void* const* d_in, const int* in_sizes, int n_in,
                              void* d_out, int out_size) {
    const float* x  = (const float*)d_in[0];   // (64, 256, 64)
    const float* Jr = (const float*)d_in[1];   // (256, 256)
    float* out = (float*)d_out;

    size_t shmem = (size_t)(128 * JS_STRIDE + 256 * AS_STRIDE) * sizeof(float);
    cudaFuncSetAttribute(gemm_step, cudaFuncAttributeMaxDynamicSharedMemorySize,
                         (int)shmem);

    build_J<<<NSPIN, NSPIN>>>(Jr);
    gemm_step<<<128, 512, shmem>>>(x, 0);   // u1 = J h           (+ m0, m1)
    gemm_step<<<136, 512, shmem>>>(x, 1);   // u2 = J u1, B2 = J J (+ m2..m4, tp2..tp4)
    newton_kernel<<<1, 64>>>(out, out_size);
}